// round 14
// baseline (speedup 1.0000x reference)
#include <cuda_runtime.h>
#include <cuda_bf16.h>
#include <cstdint>

#define HIDDEN 1024
#define BATCH 8
#define SEQ 2048
#define MTOT (BATCH * SEQ)          // 16384 rows
#define NEG_INF -1e38f
#define CH (BATCH * HIDDEN)         // 8192 channels
#define LCHUNK 64
#define NCHUNK (SEQ / LCHUNK)       // 32
#define QMAXF 16256.0f              // 127 * 128

// GEMM tiling (imma m16n8k32, int8 2-limb)
#define BM 128
#define BN 128
#define BK 64
#define KITER (HIDDEN / BK)          // 16
#define PITCH 80
#define TILE_BYTES (BM * PITCH)      // 10240
#define A1_OFF 0
#define A0_OFF TILE_BYTES
#define B1_OFF (2 * TILE_BYTES)
#define B0_OFF (3 * TILE_BYTES)
#define STAGE_BYTES (4 * TILE_BYTES) // 40960
#define NSTAGE 5
#define SMEM_TOTAL (NSTAGE * STAGE_BYTES)   // 204800
#define GTHREADS 512

// ---------------------------------------------------------------------------
// Scratch (device globals)
// ---------------------------------------------------------------------------
__device__ __align__(16) int8_t g_xk1[MTOT * HIDDEN];
__device__ __align__(16) int8_t g_xk0[MTOT * HIDDEN];
__device__ __align__(16) int8_t g_xv1[MTOT * HIDDEN];
__device__ __align__(16) int8_t g_xv0[MTOT * HIDDEN];
__device__ __align__(16) int8_t g_xr1[MTOT * HIDDEN];
__device__ __align__(16) int8_t g_xr0[MTOT * HIDDEN];
__device__ __align__(16) int8_t g_o1 [MTOT * HIDDEN];
__device__ __align__(16) int8_t g_o0 [MTOT * HIDDEN];

__device__ __align__(16) int8_t g_Wk1[HIDDEN * HIDDEN];
__device__ __align__(16) int8_t g_Wk0[HIDDEN * HIDDEN];
__device__ __align__(16) int8_t g_Wv1[HIDDEN * HIDDEN];
__device__ __align__(16) int8_t g_Wv0[HIDDEN * HIDDEN];
__device__ __align__(16) int8_t g_Wr1[HIDDEN * HIDDEN];
__device__ __align__(16) int8_t g_Wr0[HIDDEN * HIDDEN];
__device__ __align__(16) int8_t g_Wo1[HIDDEN * HIDDEN];
__device__ __align__(16) int8_t g_Wo0[HIDDEN * HIDDEN];

__device__ float g_k[MTOT * HIDDEN];
__device__ float g_v[MTOT * HIDDEN];
__device__ float g_r[MTOT * HIDDEN];

__device__ float g_saa[CH * NCHUNK];
__device__ float g_sbb[CH * NCHUNK];
__device__ float g_spp[CH * NCHUNK];
__device__ float g_iaa[CH * NCHUNK];
__device__ float g_ibb[CH * NCHUNK];
__device__ float g_ipp[CH * NCHUNK];

// fine-grained scales
__device__ float g_xsc[MTOT];          // per token-row absmax of x (bounds mixes)
__device__ float g_wsc[4 * HIDDEN];    // per output-row absmax of each W
__device__ unsigned g_svb;             // global max|v| (bounds r*wkv)

// ---------------------------------------------------------------------------
// Helpers
// ---------------------------------------------------------------------------
__device__ __forceinline__ uint32_t smem_u32(const void* p) {
    uint32_t a;
    asm("{ .reg .u64 t; cvta.to.shared.u64 t, %1; cvt.u32.u64 %0, t; }"
        : "=r"(a) : "l"(p));
    return a;
}

__device__ __forceinline__ void cp16(uint32_t s, const void* g) {
    asm volatile("cp.async.cg.shared.global [%0], [%1], 16;" :: "r"(s), "l"(g));
}

// volatile is load-bearing: non-volatile "+r" MMA asm was observed (R13) to
// change results (compiler rematerialization duplicating accumulation).
#define MMA_S8(c, a, b)                                                       \
    asm volatile(                                                             \
        "mma.sync.aligned.m16n8k32.row.col.s32.s8.s8.s32 "                    \
        "{%0,%1,%2,%3},{%4,%5,%6,%7},{%8,%9},{%0,%1,%2,%3};"                  \
        : "+r"((c)[0]), "+r"((c)[1]), "+r"((c)[2]), "+r"((c)[3])              \
        : "r"((a)[0]), "r"((a)[1]), "r"((a)[2]), "r"((a)[3]),                 \
          "r"((b)[0]), "r"((b)[1]))

#define LDMATRIX_X4(r0, r1, r2, r3, addr)                                     \
    asm volatile(                                                             \
        "ldmatrix.sync.aligned.m8n8.x4.shared.b16 {%0,%1,%2,%3}, [%4];"       \
        : "=r"(r0), "=r"(r1), "=r"(r2), "=r"(r3) : "r"(addr))

__device__ __forceinline__ void quant4(const float* v, float inv,
                                       uint32_t& p1, uint32_t& p0) {
    uint32_t r1 = 0, r0 = 0;
#pragma unroll
    for (int j = 0; j < 4; j++) {
        float q = rintf(v[j] * inv);
        q = fminf(fmaxf(q, -QMAXF), QMAXF);
        float q1 = rintf(q * 0.0078125f);      // /128
        float q0 = q - 128.0f * q1;
        r1 |= ((uint32_t)(uint8_t)(int8_t)(int)q1) << (j * 8);
        r0 |= ((uint32_t)(uint8_t)(int8_t)(int)q0) << (j * 8);
    }
    p1 = r1; p0 = r0;
}

__device__ __forceinline__ float amax4(float4 v) {
    return fmaxf(fmaxf(fabsf(v.x), fabsf(v.y)), fmaxf(fabsf(v.z), fabsf(v.w)));
}

// ---------------------------------------------------------------------------
// 1) Prep: 4 token rows per block (x read 1.25x instead of 2x)
//    blocks [0, MTOT/4): x-quant; blocks [MTOT/4, MTOT/4+4096): weight quant
// ---------------------------------------------------------------------------
__global__ void prep_quant(const float* __restrict__ x,
                           const float* __restrict__ mk,
                           const float* __restrict__ mv,
                           const float* __restrict__ mr,
                           const float* __restrict__ W0, const float* __restrict__ W1,
                           const float* __restrict__ W2, const float* __restrict__ W3) {
    __shared__ float sred4[4][8];
    __shared__ float sbc4[4];
    const int blk = blockIdx.x;
    const int tid = threadIdx.x;
    const int lane = tid & 31;
    const int wrp = tid >> 5;
    if (blk == 0 && tid == 0) g_svb = 0;

    if (blk < MTOT / 4) {
        const int m0 = blk * 4;
        const int c4 = tid * 4;
        const int t0 = m0 & (SEQ - 1);

        float4 xr[4];
#pragma unroll
        for (int i = 0; i < 4; i++)
            xr[i] = *reinterpret_cast<const float4*>(x + (size_t)(m0 + i) * HIDDEN + c4);
        float4 xpv = (t0 == 0) ? make_float4(0.f, 0.f, 0.f, 0.f)
                               : *reinterpret_cast<const float4*>(x + (size_t)(m0 - 1) * HIDDEN + c4);

        // per-row local maxima: max(|x_t|, |x_{t-1}|)
        float rm[4];
        rm[0] = fmaxf(amax4(xr[0]), amax4(xpv));
        rm[1] = fmaxf(amax4(xr[1]), amax4(xr[0]));
        rm[2] = fmaxf(amax4(xr[2]), amax4(xr[1]));
        rm[3] = fmaxf(amax4(xr[3]), amax4(xr[2]));

        // block reduction of 4 maxima
#pragma unroll
        for (int i = 0; i < 4; i++) {
            float m = rm[i];
#pragma unroll
            for (int o = 16; o > 0; o >>= 1)
                m = fmaxf(m, __shfl_xor_sync(0xFFFFFFFF, m, o));
            if (lane == 0) sred4[i][wrp] = m;
        }
        __syncthreads();
        if (tid < 32) {
#pragma unroll
            for (int i = 0; i < 4; i++) {
                float m = (lane < 8) ? sred4[i][lane] : 0.f;
#pragma unroll
                for (int o = 4; o > 0; o >>= 1)
                    m = fmaxf(m, __shfl_xor_sync(0xFFFFFFFF, m, o));
                if (lane == 0) sbc4[i] = m;
            }
        }
        __syncthreads();
        if (tid < 4) g_xsc[m0 + tid] = sbc4[tid];

        float4 k4 = *reinterpret_cast<const float4*>(mk + c4);
        float4 v4 = *reinterpret_cast<const float4*>(mv + c4);
        float4 r4 = *reinterpret_cast<const float4*>(mr + c4);
        const float kf[4] = {k4.x, k4.y, k4.z, k4.w};
        const float vf[4] = {v4.x, v4.y, v4.z, v4.w};
        const float rf[4] = {r4.x, r4.y, r4.z, r4.w};

#pragma unroll
        for (int i = 0; i < 4; i++) {
            float rmax = sbc4[i];
            float inv = (rmax > 0.f) ? (QMAXF / rmax) : 0.f;
            float4 cur = xr[i];
            float4 prv = (i == 0) ? xpv : xr[i - 1];
            float xcf[4] = {cur.x, cur.y, cur.z, cur.w};
            float xpf[4] = {prv.x, prv.y, prv.z, prv.w};
            float ok[4], ov[4], orr[4];
#pragma unroll
            for (int j = 0; j < 4; j++) {
                ok[j]  = xcf[j] * kf[j] + xpf[j] * (1.f - kf[j]);
                ov[j]  = xcf[j] * vf[j] + xpf[j] * (1.f - vf[j]);
                orr[j] = xcf[j] * rf[j] + xpf[j] * (1.f - rf[j]);
            }
            size_t idx = (size_t)(m0 + i) * HIDDEN + c4;
            uint32_t p1, p0;
            quant4(ok, inv, p1, p0);
            *reinterpret_cast<uint32_t*>(g_xk1 + idx) = p1;
            *reinterpret_cast<uint32_t*>(g_xk0 + idx) = p0;
            quant4(ov, inv, p1, p0);
            *reinterpret_cast<uint32_t*>(g_xv1 + idx) = p1;
            *reinterpret_cast<uint32_t*>(g_xv0 + idx) = p0;
            quant4(orr, inv, p1, p0);
            *reinterpret_cast<uint32_t*>(g_xr1 + idx) = p1;
            *reinterpret_cast<uint32_t*>(g_xr0 + idx) = p0;
        }
    } else {
        int w = blk - MTOT / 4;            // 0..4095
        int sel = w >> 10;
        int n = w & (HIDDEN - 1);
        const float* W; int8_t *d1, *d0;
        switch (sel) {
            case 0: W = W0; d1 = g_Wk1; d0 = g_Wk0; break;
            case 1: W = W1; d1 = g_Wv1; d0 = g_Wv0; break;
            case 2: W = W2; d1 = g_Wr1; d0 = g_Wr0; break;
            default: W = W3; d1 = g_Wo1; d0 = g_Wo0; break;
        }
        size_t idx = (size_t)n * HIDDEN + tid * 4;
        float4 wvv = *reinterpret_cast<const float4*>(W + idx);
        float m = amax4(wvv);
#pragma unroll
        for (int o = 16; o > 0; o >>= 1)
            m = fmaxf(m, __shfl_xor_sync(0xFFFFFFFF, m, o));
        if (lane == 0) sred4[0][wrp] = m;
        __syncthreads();
        if (tid < 32) {
            float mm = (lane < 8) ? sred4[0][lane] : 0.f;
#pragma unroll
            for (int o = 4; o > 0; o >>= 1)
                mm = fmaxf(mm, __shfl_xor_sync(0xFFFFFFFF, mm, o));
            if (lane == 0) sbc4[0] = mm;
        }
        __syncthreads();
        float rmax = sbc4[0];
        if (tid == 0) g_wsc[w] = rmax;
        float inv = (rmax > 0.f) ? (QMAXF / rmax) : 0.f;

        float wf[4] = {wvv.x, wvv.y, wvv.z, wvv.w};
        uint32_t p1, p0;
        quant4(wf, inv, p1, p0);
        *reinterpret_cast<uint32_t*>(d1 + idx) = p1;
        *reinterpret_cast<uint32_t*>(d0 + idx) = p0;
    }
}

// ---------------------------------------------------------------------------
// 2) int8 IMMA GEMM (R12 mainloop: volatile MMA, interleaved passes)
// ---------------------------------------------------------------------------
template <bool FUSED>
__global__ __launch_bounds__(GTHREADS, 1)
void gemm_imma(float* __restrict__ outC) {
    extern __shared__ __align__(128) char smem[];
    __shared__ unsigned s_vmax;

    const int8_t *A1g, *A0g, *B1g, *B0g;
    float* C;
    const float* wscp;
    float sA = 0.f;
    bool sigmoid = false, vmax = false;
    if (FUSED) {
        int z = blockIdx.z;
        wscp = g_wsc + z * HIDDEN;
        if (z == 0)      { A1g = g_xk1; A0g = g_xk0; B1g = g_Wk1; B0g = g_Wk0; C = g_k; }
        else if (z == 1) { A1g = g_xv1; A0g = g_xv0; B1g = g_Wv1; B0g = g_Wv0; C = g_v; vmax = true; }
        else             { A1g = g_xr1; A0g = g_xr0; B1g = g_Wr1; B0g = g_Wr0; C = g_r; sigmoid = true; }
    } else {
        A1g = g_o1; A0g = g_o0; B1g = g_Wo1; B0g = g_Wo0; C = outC;
        wscp = g_wsc + 3 * HIDDEN;
        sA = __uint_as_float(g_svb);
    }
    const float qi2 = 1.0f / (QMAXF * QMAXF);

    const int tid = threadIdx.x;
    const int wid = tid >> 5;
    const int lane = tid & 31;
    const int wm = wid >> 2;
    const int wn = wid & 3;
    const int gr = lane >> 2;
    const int tg = (lane & 3) * 2;
    const int bm = blockIdx.y * BM;
    const int bn = blockIdx.x * BN;
    const uint32_t sbase = smem_u32(smem);

    if (vmax && tid == 0) s_vmax = 0;

    const int a_row = lane & 15;
    const int a_kB  = (lane >> 4) * 16;
    const int b_row = (lane & 7) + ((lane >> 4) & 1) * 8;
    const int b_kB  = ((lane >> 3) & 1) * 16;

    const int l_row = tid >> 2;
    const int l_ch  = tid & 3;
    auto load_stage = [&](int c, int stg) {
        const uint32_t sb = sbase + stg * STAGE_BYTES;
        const int k0 = c * BK;
        uint32_t so = l_row * PITCH + l_ch * 16;
        size_t ga = (size_t)(bm + l_row) * HIDDEN + k0 + l_ch * 16;
        size_t gb = (size_t)(bn + l_row) * HIDDEN + k0 + l_ch * 16;
        cp16(sb + A1_OFF + so, A1g + ga);
        cp16(sb + A0_OFF + so, A0g + ga);
        cp16(sb + B1_OFF + so, B1g + gb);
        cp16(sb + B0_OFF + so, B0g + gb);
        asm volatile("cp.async.commit_group;" ::: "memory");
    };

    int P2[2][4][4], P1[2][4][4];
#pragma unroll
    for (int i = 0; i < 2; i++)
#pragma unroll
        for (int j = 0; j < 4; j++)
#pragma unroll
            for (int q = 0; q < 4; q++) { P2[i][j][q] = 0; P1[i][j][q] = 0; }

    load_stage(0, 0);
    load_stage(1, 1);
    load_stage(2, 2);

    int stg = 0, nstg = 3;
#pragma unroll 1
    for (int c = 0; c < KITER; c++) {
        if ((c & 1) == 0) __syncthreads();

        if (c + 3 < KITER) load_stage(c + 3, nstg);
        else asm volatile("cp.async.commit_group;" ::: "memory");

        asm volatile("cp.async.wait_group 3;" ::: "memory");

        const uint32_t sb = sbase + stg * STAGE_BYTES;
        if (++stg == NSTAGE) stg = 0;
        if (++nstg == NSTAGE) nstg = 0;

#pragma unroll
        for (int kh = 0; kh < 2; kh++) {
            const int kb = kh * 32;
            uint32_t b1f[4][2], b0f[4][2];
#pragma unroll
            for (int np = 0; np < 2; np++) {
                int n0 = wn * 32 + np * 16;
                uint32_t ro = (uint32_t)(n0 + b_row) * PITCH + kb + b_kB;
                LDMATRIX_X4(b1f[np * 2][0], b1f[np * 2][1],
                            b1f[np * 2 + 1][0], b1f[np * 2 + 1][1], sb + B1_OFF + ro);
                LDMATRIX_X4(b0f[np * 2][0], b0f[np * 2][1],
                            b0f[np * 2 + 1][0], b0f[np * 2 + 1][1], sb + B0_OFF + ro);
            }
#pragma unroll
            for (int mf = 0; mf < 2; mf++) {
                int r0 = wm * 32 + mf * 16;
                uint32_t ro = (uint32_t)(r0 + a_row) * PITCH + kb + a_kB;
                uint32_t a1f[4], a0f[4];
                LDMATRIX_X4(a1f[0], a1f[1], a1f[2], a1f[3], sb + A1_OFF + ro);
                LDMATRIX_X4(a0f[0], a0f[1], a0f[2], a0f[3], sb + A0_OFF + ro);
#pragma unroll
                for (int nf = 0; nf < 4; nf++) {
                    MMA_S8(P2[mf][nf], a1f, b1f[nf]);
                    MMA_S8(P1[mf][nf], a1f, b0f[nf]);
                    MMA_S8(P1[mf][nf], a0f, b1f[nf]);
                }
            }
        }
    }

    // epilogue: per-row (A) x per-col (B) scales
    float lmax = 0.f;
#pragma unroll
    for (int mf = 0; mf < 2; mf++) {
        int r0 = bm + wm * 32 + mf * 16 + gr;
        float ra = FUSED ? g_xsc[r0] : sA;
        float rb = FUSED ? g_xsc[r0 + 8] : sA;
#pragma unroll
        for (int nf = 0; nf < 4; nf++) {
            int cc = bn + wn * 32 + nf * 8 + tg;
            float cs0 = wscp[cc] * qi2;
            float cs1 = wscp[cc + 1] * qi2;
            float cv[4];
            cv[0] = ra * cs0 * (16384.0f * (float)P2[mf][nf][0] + 128.0f * (float)P1[mf][nf][0]);
            cv[1] = ra * cs1 * (16384.0f * (float)P2[mf][nf][1] + 128.0f * (float)P1[mf][nf][1]);
            cv[2] = rb * cs0 * (16384.0f * (float)P2[mf][nf][2] + 128.0f * (float)P1[mf][nf][2]);
            cv[3] = rb * cs1 * (16384.0f * (float)P2[mf][nf][3] + 128.0f * (float)P1[mf][nf][3]);
#pragma unroll
            for (int q = 0; q < 4; q++) {
                if (FUSED && vmax) lmax = fmaxf(lmax, fabsf(cv[q]));
                if (FUSED && sigmoid) cv[q] = 1.f / (1.f + __expf(-cv[q]));
            }
            *reinterpret_cast<float2*>(C + (size_t)r0 * HIDDEN + cc) = make_float2(cv[0], cv[1]);
            *reinterpret_cast<float2*>(C + (size_t)(r0 + 8) * HIDDEN + cc) = make_float2(cv[2], cv[3]);
        }
    }

    if (FUSED && vmax) {
        __syncthreads();
#pragma unroll
        for (int o = 16; o > 0; o >>= 1)
            lmax = fmaxf(lmax, __shfl_xor_sync(0xFFFFFFFF, lmax, o));
        if (lane == 0) atomicMax(&s_vmax, __float_as_uint(lmax));
        __syncthreads();
        if (tid == 0) atomicMax(&g_svb, s_vmax);
    }
}

// ---------------------------------------------------------------------------
// 3) Chunk-parallel WKV scan
// ---------------------------------------------------------------------------
__global__ void wkv_phase1(const float* __restrict__ td) {
    int idx = blockIdx.x * blockDim.x + threadIdx.x;   // over CH*NCHUNK/4
    if (idx >= CH * NCHUNK / 4) return;
    int h4 = (idx & 255) * 4;
    int bc = idx >> 8;                  // b * NCHUNK + c
    int c = bc & (NCHUNK - 1);
    int b = bc >> 5;

    float4 w4 = *reinterpret_cast<const float4*>(td + h4);
    const float wv[4] = {w4.x, w4.y, w4.z, w4.w};

    const size_t base = ((size_t)b * SEQ + (size_t)c * LCHUNK) * HIDDEN + h4;
    const float* kp = g_k + base;
    const float* vp = g_v + base;

    float aa[4], bb[4], pp[4];
#pragma unroll
    for (int j = 0; j < 4; j++) { aa[j] = 0.f; bb[j] = 0.f; pp[j] = NEG_INF; }

#pragma unroll 2
    for (int t = 0; t < LCHUNK; t++) {
        float4 k4 = *reinterpret_cast<const float4*>(kp + (size_t)t * HIDDEN);
        float4 v4 = *reinterpret_cast<const float4*>(vp + (size_t)t * HIDDEN);
        float kf[4] = {k4.x, k4.y, k4.z, k4.w};
        float vf[4] = {v4.x, v4.y, v4.z, v4.w};
#pragma unroll
        for (int j = 0; j < 4; j++) {
            float ww2 = wv[j] + pp[j];
            float p2 = fmaxf(ww2, kf[j]);
            float e1 = __expf(ww2 - p2);
            float e2 = __expf(kf[j] - p2);
            aa[j] = e1 * aa[j] + e2 * vf[j];
            bb[j] = e1 * bb[j] + e2;
            pp[j] = p2;
        }
    }
    int s = bc * HIDDEN + h4;
    *reinterpret_cast<float4*>(g_saa + s) = make_float4(aa[0], aa[1], aa[2], aa[3]);
    *reinterpret_cast<float4*>(g_sbb + s) = make_float4(bb[0], bb[1], bb[2], bb[3]);
    *reinterpret_cast<float4*>(g_spp + s) = make_float4(pp[0], pp[1], pp[2], pp[3]);
}

// Warp Kogge-Stone scan over chunks: one warp per (b,h) channel, lane = chunk.
__global__ void wkv_phase2(const float* __restrict__ td) {
    int gwarp = (blockIdx.x * blockDim.x + threadIdx.x) >> 5;
    if (gwarp >= CH) return;
    int lane = threadIdx.x & 31;
    int h = gwarp & (HIDDEN - 1);
    int b = gwarp >> 10;
    const float w = td[h];

    int s = (b * NCHUNK + lane) * HIDDEN + h;
    float aa = g_saa[s], bb = g_sbb[s], pp = g_spp[s];

#pragma unroll
    for (int d = 1; d < NCHUNK; d <<= 1) {
        float oaa = __shfl_up_sync(0xFFFFFFFF, aa, d);
        float obb = __shfl_up_sync(0xFFFFFFFF, bb, d);
        float opp = __shfl_up_sync(0xFFFFFFFF, pp, d);
        if (lane >= d) {
            float sp = opp + w * (float)(d * LCHUNK);
            float p = fmaxf(sp, pp);
            float e1 = __expf(sp - p);
            float e2 = __expf(pp - p);
            aa = e1 * oaa + e2 * aa;
            bb = e1 * obb + e2 * bb;
            pp = p;
        }
    }

    // exclusive prefix
    float exaa = __shfl_up_sync(0xFFFFFFFF, aa, 1);
    float exbb = __shfl_up_sync(0xFFFFFFFF, bb, 1);
    float expp = __shfl_up_sync(0xFFFFFFFF, pp, 1);
    if (lane == 0) { exaa = 0.f; exbb = 0.f; expp = NEG_INF; }
    g_iaa[s] = exaa;
    g_ibb[s] = exbb;
    g_ipp[s] = expp;
}

__global__ void wkv_phase3(const float* __restrict__ td,
                           const float* __restrict__ tf) {
    int idx = blockIdx.x * blockDim.x + threadIdx.x;   // over CH*NCHUNK/4
    if (idx >= CH * NCHUNK / 4) return;
    int h4 = (idx & 255) * 4;
    int bc = idx >> 8;
    int c = bc & (NCHUNK - 1);
    int b = bc >> 5;

    float4 w4 = *reinterpret_cast<const float4*>(td + h4);
    float4 u4 = *reinterpret_cast<const float4*>(tf + h4);
    const float wv[4] = {w4.x, w4.y, w4.z, w4.w};
    const float uv[4] = {u4.x, u4.y, u4.z, u4.w};

    float sv = __uint_as_float(g_svb);
    float inv = (sv > 0.f) ? (QMAXF / sv) : 0.f;

    const size_t base = ((size_t)b * SEQ + (size_t)c * LCHUNK) * HIDDEN + h4;
    const float* kp = g_k + base;
    const float* vp = g_v + base;
    const float* rp = g_r + base;

    int s = bc * HIDDEN + h4;
    float4 a4 = *reinterpret_cast<const float4*>(g_iaa + s);
    float4 b4 = *reinterpret_cast<const float4*>(g_ibb + s);
    float4 p4 = *reinterpret_cast<const float4*>(g_ipp + s);
    float aa[4] = {a4.x, a4.y, a4.z, a4.w};
    float bb[4] = {b4.x, b4.y, b4.z, b4.w};
    float pp[4] = {p4.x, p4.y, p4.z, p4.w};

#pragma unroll 2
    for (int t = 0; t < LCHUNK; t++) {
        size_t off = (size_t)t * HIDDEN;
        float4 k4 = *reinterpret_cast<const float4*>(kp + off);
        float4 v4 = *reinterpret_cast<const float4*>(vp + off);
        float4 r4 = *reinterpret_cast<const float4*>(rp + off);
        float kf[4] = {k4.x, k4.y, k4.z, k4.w};
        float vf[4] = {v4.x, v4.y, v4.z, v4.w};
        float rf[4] = {r4.x, r4.y, r4.z, r4.w};
        uint32_t o1 = 0, o0 = 0;
#pragma unroll
        for (int j = 0; j < 4; j++) {
            float ww = uv[j] + kf[j];
            float p = fmaxf(pp[j], ww);
            float e1 = __expf(pp[j] - p);
            float e2 = __expf(ww - p);
            float wkv = (e1 * aa[j] + e2 * vf[j]) / (e1 * bb[j] + e2 + 1e-9f);
            float o = rf[j] * wkv;

            float q = rintf(o * inv);
            q = fminf(fmaxf(q, -QMAXF), QMAXF);
            float q1 = rintf(q * 0.0078125f);
            float q0 = q - 128.0f * q1;
            o1 |= ((uint32_t)(uint8_t)(int8_t)(int)q1) << (j * 8);
            o0 |= ((uint32_t)(uint8_t)(int8_t)(int)q0) << (j * 8);

            float ww2 = wv[j] + pp[j];
            float p2 = fmaxf(ww2, kf[j]);
            float e1b = __expf(ww2 - p2);
            float e2b = __expf(kf[j] - p2);
            aa[j] = e1b * aa[j] + e2b * vf[j];
            bb[j] = e1b * bb[j] + e2b;
            pp[j] = p2;
        }
        *reinterpret_cast<uint32_t*>(g_o1 + base + off) = o1;
        *reinterpret_cast<uint32_t*>(g_o0 + base + off) = o0;
    }
}

// ---------------------------------------------------------------------------
// Launch
// ---------------------------------------------------------------------------
extern "C" void kernel_launch(void* const* d_in, const int* in_sizes, int n_in,
                              void* d_out, int out_size) {
    const float* x  = (const float*)d_in[0];
    const float* td = (const float*)d_in[1];
    const float* tf = (const float*)d_in[2];
    const float* mk = (const float*)d_in[3];
    const float* mv = (const float*)d_in[4];
    const float* mr = (const float*)d_in[5];
    const float* Wk = (const float*)d_in[6];
    const float* Wv = (const float*)d_in[7];
    const float* Wr = (const float*)d_in[8];
    const float* Wo = (const float*)d_in[9];
    float* out = (float*)d_out;

    cudaFuncSetAttribute(gemm_imma<true>,  cudaFuncAttributeMaxDynamicSharedMemorySize, SMEM_TOTAL);
    cudaFuncSetAttribute(gemm_imma<false>, cudaFuncAttributeMaxDynamicSharedMemorySize, SMEM_TOTAL);

    // 1) prep: 4-rows-per-block mix quant + per-row weight quant (resets g_svb)
    prep_quant<<<MTOT / 4 + 4 * HIDDEN, 256>>>(x, mk, mv, mr, Wk, Wv, Wr, Wo);

    // 2) fused k/v/r projections (int8 imma)
    dim3 ggrid(HIDDEN / BN, MTOT / BM, 3);   // (8, 128, 3)
    gemm_imma<true><<<ggrid, GTHREADS, SMEM_TOTAL>>>(nullptr);

    // 3) chunk-parallel wkv
    wkv_phase1<<<(CH * NCHUNK / 4 + 255) / 256, 256>>>(td);
    wkv_phase2<<<(CH * 32 + 255) / 256, 256>>>(td);   // one warp per channel
    wkv_phase3<<<(CH * NCHUNK / 4 + 255) / 256, 256>>>(td, tf);

    // 4) output projection
    dim3 ogrid(HIDDEN / BN, MTOT / BM, 1);
    gemm_imma<false><<<ogrid, GTHREADS, SMEM_TOTAL>>>(out);
}

// round 15
// speedup vs baseline: 1.0222x; 1.0222x over previous
#include <cuda_runtime.h>
#include <cuda_bf16.h>
#include <cstdint>

#define HIDDEN 1024
#define BATCH 8
#define SEQ 2048
#define MTOT (BATCH * SEQ)          // 16384 rows
#define NEG_INF -1e38f
#define CH (BATCH * HIDDEN)         // 8192 channels
#define LCHUNK 64
#define NCHUNK (SEQ / LCHUNK)       // 32
#define QMAXF 16256.0f              // 127 * 128

// GEMM tiling (imma m16n8k32, int8 2-limb)
#define BM 128
#define BN 128
#define BK 64
#define KITER (HIDDEN / BK)          // 16
#define PITCH 80
#define TILE_BYTES (BM * PITCH)      // 10240
#define A1_OFF 0
#define A0_OFF TILE_BYTES
#define B1_OFF (2 * TILE_BYTES)
#define B0_OFF (3 * TILE_BYTES)
#define STAGE_BYTES (4 * TILE_BYTES) // 40960
#define NSTAGE 5
#define SMEM_TOTAL (NSTAGE * STAGE_BYTES)   // 204800
#define GTHREADS 512

// fused wkv kernel geometry
#define WKV_BLOCKS 256
#define WKV_THREADS 256

// ---------------------------------------------------------------------------
// Scratch (device globals)
// ---------------------------------------------------------------------------
__device__ __align__(16) int8_t g_xk1[MTOT * HIDDEN];
__device__ __align__(16) int8_t g_xk0[MTOT * HIDDEN];
__device__ __align__(16) int8_t g_xv1[MTOT * HIDDEN];
__device__ __align__(16) int8_t g_xv0[MTOT * HIDDEN];
__device__ __align__(16) int8_t g_xr1[MTOT * HIDDEN];
__device__ __align__(16) int8_t g_xr0[MTOT * HIDDEN];
__device__ __align__(16) int8_t g_o1 [MTOT * HIDDEN];
__device__ __align__(16) int8_t g_o0 [MTOT * HIDDEN];

__device__ __align__(16) int8_t g_Wk1[HIDDEN * HIDDEN];
__device__ __align__(16) int8_t g_Wk0[HIDDEN * HIDDEN];
__device__ __align__(16) int8_t g_Wv1[HIDDEN * HIDDEN];
__device__ __align__(16) int8_t g_Wv0[HIDDEN * HIDDEN];
__device__ __align__(16) int8_t g_Wr1[HIDDEN * HIDDEN];
__device__ __align__(16) int8_t g_Wr0[HIDDEN * HIDDEN];
__device__ __align__(16) int8_t g_Wo1[HIDDEN * HIDDEN];
__device__ __align__(16) int8_t g_Wo0[HIDDEN * HIDDEN];

__device__ float g_k[MTOT * HIDDEN];
__device__ float g_v[MTOT * HIDDEN];
__device__ float g_r[MTOT * HIDDEN];

__device__ float g_saa[CH * NCHUNK];
__device__ float g_sbb[CH * NCHUNK];
__device__ float g_spp[CH * NCHUNK];
__device__ float g_iaa[CH * NCHUNK];
__device__ float g_ibb[CH * NCHUNK];
__device__ float g_ipp[CH * NCHUNK];

// fine-grained scales
__device__ float g_xsc[MTOT];          // per token-row absmax of x (bounds mixes)
__device__ float g_wsc[4 * HIDDEN];    // per output-row absmax of each W
__device__ unsigned g_svb;             // global max|v| (bounds r*wkv)

// grid-barrier counters for the fused wkv kernel (reset in prep each call)
__device__ unsigned g_bar1;
__device__ unsigned g_bar2;

// ---------------------------------------------------------------------------
// Helpers
// ---------------------------------------------------------------------------
__device__ __forceinline__ uint32_t smem_u32(const void* p) {
    uint32_t a;
    asm("{ .reg .u64 t; cvta.to.shared.u64 t, %1; cvt.u32.u64 %0, t; }"
        : "=r"(a) : "l"(p));
    return a;
}

__device__ __forceinline__ void cp16(uint32_t s, const void* g) {
    asm volatile("cp.async.cg.shared.global [%0], [%1], 16;" :: "r"(s), "l"(g));
}

#define MMA_S8(c, a, b)                                                       \
    asm volatile(                                                             \
        "mma.sync.aligned.m16n8k32.row.col.s32.s8.s8.s32 "                    \
        "{%0,%1,%2,%3},{%4,%5,%6,%7},{%8,%9},{%0,%1,%2,%3};"                  \
        : "+r"((c)[0]), "+r"((c)[1]), "+r"((c)[2]), "+r"((c)[3])              \
        : "r"((a)[0]), "r"((a)[1]), "r"((a)[2]), "r"((a)[3]),                 \
          "r"((b)[0]), "r"((b)[1]))

#define LDMATRIX_X4(r0, r1, r2, r3, addr)                                     \
    asm volatile(                                                             \
        "ldmatrix.sync.aligned.m8n8.x4.shared.b16 {%0,%1,%2,%3}, [%4];"       \
        : "=r"(r0), "=r"(r1), "=r"(r2), "=r"(r3) : "r"(addr))

__device__ __forceinline__ void quant4(const float* v, float inv,
                                       uint32_t& p1, uint32_t& p0) {
    uint32_t r1 = 0, r0 = 0;
#pragma unroll
    for (int j = 0; j < 4; j++) {
        float q = rintf(v[j] * inv);
        q = fminf(fmaxf(q, -QMAXF), QMAXF);
        float q1 = rintf(q * 0.0078125f);      // /128
        float q0 = q - 128.0f * q1;
        r1 |= ((uint32_t)(uint8_t)(int8_t)(int)q1) << (j * 8);
        r0 |= ((uint32_t)(uint8_t)(int8_t)(int)q0) << (j * 8);
    }
    p1 = r1; p0 = r0;
}

// block max over 256 threads; returns broadcast value
__device__ __forceinline__ float block_max256(float m, float* sred, float* sbc) {
    int tid = threadIdx.x;
#pragma unroll
    for (int o = 16; o > 0; o >>= 1)
        m = fmaxf(m, __shfl_xor_sync(0xFFFFFFFF, m, o));
    if ((tid & 31) == 0) sred[tid >> 5] = m;
    __syncthreads();
    if (tid < 8) {
        m = sred[tid];
#pragma unroll
        for (int o = 4; o > 0; o >>= 1)
            m = fmaxf(m, __shfl_xor_sync(0xFF, m, o));
        if (tid == 0) *sbc = m;
    }
    __syncthreads();
    return *sbc;
}

// all-block barrier (co-residency guaranteed: WKV_BLOCKS=256, tiny blocks)
__device__ __forceinline__ void grid_barrier(unsigned* ctr) {
    __syncthreads();
    __threadfence();
    if (threadIdx.x == 0) {
        atomicAdd(ctr, 1u);
        while (*(volatile unsigned*)ctr < WKV_BLOCKS) { }
    }
    __syncthreads();
}

// ---------------------------------------------------------------------------
// 1) Prep: per-row mix quant (blocks 0..16383) + per-row weight quant
//    (R12 version; also resets g_svb and the wkv grid-barrier counters)
// ---------------------------------------------------------------------------
__global__ void prep_quant(const float* __restrict__ x,
                           const float* __restrict__ mk,
                           const float* __restrict__ mv,
                           const float* __restrict__ mr,
                           const float* __restrict__ W0, const float* __restrict__ W1,
                           const float* __restrict__ W2, const float* __restrict__ W3) {
    __shared__ float sred[8];
    __shared__ float sbc;
    int blk = blockIdx.x;
    int tid = threadIdx.x;
    if (blk == 0 && tid == 0) { g_svb = 0; g_bar1 = 0; g_bar2 = 0; }

    if (blk < MTOT) {
        int m = blk;
        int t = m & (SEQ - 1);
        size_t idx = (size_t)m * HIDDEN + tid * 4;
        int h = tid * 4;

        float4 xc = *reinterpret_cast<const float4*>(x + idx);
        float4 xp = (t == 0) ? make_float4(0.f, 0.f, 0.f, 0.f)
                             : *reinterpret_cast<const float4*>(x + idx - HIDDEN);

        float lm = fmaxf(fmaxf(fmaxf(fabsf(xc.x), fabsf(xc.y)),
                               fmaxf(fabsf(xc.z), fabsf(xc.w))),
                         fmaxf(fmaxf(fabsf(xp.x), fabsf(xp.y)),
                               fmaxf(fabsf(xp.z), fabsf(xp.w))));
        float rmax = block_max256(lm, sred, &sbc);
        if (tid == 0) g_xsc[m] = rmax;
        float inv = (rmax > 0.f) ? (QMAXF / rmax) : 0.f;

        float4 k4 = *reinterpret_cast<const float4*>(mk + h);
        float4 v4 = *reinterpret_cast<const float4*>(mv + h);
        float4 r4 = *reinterpret_cast<const float4*>(mr + h);

        float xcf[4] = {xc.x, xc.y, xc.z, xc.w};
        float xpf[4] = {xp.x, xp.y, xp.z, xp.w};
        float kf[4] = {k4.x, k4.y, k4.z, k4.w};
        float vf[4] = {v4.x, v4.y, v4.z, v4.w};
        float rf[4] = {r4.x, r4.y, r4.z, r4.w};
        float ok[4], ov[4], orr[4];
#pragma unroll
        for (int j = 0; j < 4; j++) {
            ok[j]  = xcf[j] * kf[j] + xpf[j] * (1.f - kf[j]);
            ov[j]  = xcf[j] * vf[j] + xpf[j] * (1.f - vf[j]);
            orr[j] = xcf[j] * rf[j] + xpf[j] * (1.f - rf[j]);
        }
        uint32_t p1, p0;
        quant4(ok, inv, p1, p0);
        *reinterpret_cast<uint32_t*>(g_xk1 + idx) = p1;
        *reinterpret_cast<uint32_t*>(g_xk0 + idx) = p0;
        quant4(ov, inv, p1, p0);
        *reinterpret_cast<uint32_t*>(g_xv1 + idx) = p1;
        *reinterpret_cast<uint32_t*>(g_xv0 + idx) = p0;
        quant4(orr, inv, p1, p0);
        *reinterpret_cast<uint32_t*>(g_xr1 + idx) = p1;
        *reinterpret_cast<uint32_t*>(g_xr0 + idx) = p0;
    } else {
        int w = blk - MTOT;                // 0..4095
        int sel = w >> 10;
        int n = w & (HIDDEN - 1);
        const float* W; int8_t *d1, *d0;
        switch (sel) {
            case 0: W = W0; d1 = g_Wk1; d0 = g_Wk0; break;
            case 1: W = W1; d1 = g_Wv1; d0 = g_Wv0; break;
            case 2: W = W2; d1 = g_Wr1; d0 = g_Wr0; break;
            default: W = W3; d1 = g_Wo1; d0 = g_Wo0; break;
        }
        size_t idx = (size_t)n * HIDDEN + tid * 4;
        float4 wvv = *reinterpret_cast<const float4*>(W + idx);
        float lm = fmaxf(fmaxf(fabsf(wvv.x), fabsf(wvv.y)),
                         fmaxf(fabsf(wvv.z), fabsf(wvv.w)));
        float rmax = block_max256(lm, sred, &sbc);
        if (tid == 0) g_wsc[w] = rmax;
        float inv = (rmax > 0.f) ? (QMAXF / rmax) : 0.f;

        float wf[4] = {wvv.x, wvv.y, wvv.z, wvv.w};
        uint32_t p1, p0;
        quant4(wf, inv, p1, p0);
        *reinterpret_cast<uint32_t*>(d1 + idx) = p1;
        *reinterpret_cast<uint32_t*>(d0 + idx) = p0;
    }
}

// ---------------------------------------------------------------------------
// 2) int8 IMMA GEMM (R12 mainloop, frozen)
// ---------------------------------------------------------------------------
template <bool FUSED>
__global__ __launch_bounds__(GTHREADS, 1)
void gemm_imma(float* __restrict__ outC) {
    extern __shared__ __align__(128) char smem[];
    __shared__ unsigned s_vmax;

    const int8_t *A1g, *A0g, *B1g, *B0g;
    float* C;
    const float* wscp;
    float sA = 0.f;
    bool sigmoid = false, vmax = false;
    if (FUSED) {
        int z = blockIdx.z;
        wscp = g_wsc + z * HIDDEN;
        if (z == 0)      { A1g = g_xk1; A0g = g_xk0; B1g = g_Wk1; B0g = g_Wk0; C = g_k; }
        else if (z == 1) { A1g = g_xv1; A0g = g_xv0; B1g = g_Wv1; B0g = g_Wv0; C = g_v; vmax = true; }
        else             { A1g = g_xr1; A0g = g_xr0; B1g = g_Wr1; B0g = g_Wr0; C = g_r; sigmoid = true; }
    } else {
        A1g = g_o1; A0g = g_o0; B1g = g_Wo1; B0g = g_Wo0; C = outC;
        wscp = g_wsc + 3 * HIDDEN;
        sA = __uint_as_float(g_svb);
    }
    const float qi2 = 1.0f / (QMAXF * QMAXF);

    const int tid = threadIdx.x;
    const int wid = tid >> 5;
    const int lane = tid & 31;
    const int wm = wid >> 2;
    const int wn = wid & 3;
    const int gr = lane >> 2;
    const int tg = (lane & 3) * 2;
    const int bm = blockIdx.y * BM;
    const int bn = blockIdx.x * BN;
    const uint32_t sbase = smem_u32(smem);

    if (vmax && tid == 0) s_vmax = 0;

    const int a_row = lane & 15;
    const int a_kB  = (lane >> 4) * 16;
    const int b_row = (lane & 7) + ((lane >> 4) & 1) * 8;
    const int b_kB  = ((lane >> 3) & 1) * 16;

    const int l_row = tid >> 2;
    const int l_ch  = tid & 3;
    auto load_stage = [&](int c, int stg) {
        const uint32_t sb = sbase + stg * STAGE_BYTES;
        const int k0 = c * BK;
        uint32_t so = l_row * PITCH + l_ch * 16;
        size_t ga = (size_t)(bm + l_row) * HIDDEN + k0 + l_ch * 16;
        size_t gb = (size_t)(bn + l_row) * HIDDEN + k0 + l_ch * 16;
        cp16(sb + A1_OFF + so, A1g + ga);
        cp16(sb + A0_OFF + so, A0g + ga);
        cp16(sb + B1_OFF + so, B1g + gb);
        cp16(sb + B0_OFF + so, B0g + gb);
        asm volatile("cp.async.commit_group;" ::: "memory");
    };

    int P2[2][4][4], P1[2][4][4];
#pragma unroll
    for (int i = 0; i < 2; i++)
#pragma unroll
        for (int j = 0; j < 4; j++)
#pragma unroll
            for (int q = 0; q < 4; q++) { P2[i][j][q] = 0; P1[i][j][q] = 0; }

    load_stage(0, 0);
    load_stage(1, 1);
    load_stage(2, 2);

    int stg = 0, nstg = 3;
#pragma unroll 1
    for (int c = 0; c < KITER; c++) {
        if ((c & 1) == 0) __syncthreads();

        if (c + 3 < KITER) load_stage(c + 3, nstg);
        else asm volatile("cp.async.commit_group;" ::: "memory");

        asm volatile("cp.async.wait_group 3;" ::: "memory");

        const uint32_t sb = sbase + stg * STAGE_BYTES;
        if (++stg == NSTAGE) stg = 0;
        if (++nstg == NSTAGE) nstg = 0;

#pragma unroll
        for (int kh = 0; kh < 2; kh++) {
            const int kb = kh * 32;
            uint32_t b1f[4][2], b0f[4][2];
#pragma unroll
            for (int np = 0; np < 2; np++) {
                int n0 = wn * 32 + np * 16;
                uint32_t ro = (uint32_t)(n0 + b_row) * PITCH + kb + b_kB;
                LDMATRIX_X4(b1f[np * 2][0], b1f[np * 2][1],
                            b1f[np * 2 + 1][0], b1f[np * 2 + 1][1], sb + B1_OFF + ro);
                LDMATRIX_X4(b0f[np * 2][0], b0f[np * 2][1],
                            b0f[np * 2 + 1][0], b0f[np * 2 + 1][1], sb + B0_OFF + ro);
            }
#pragma unroll
            for (int mf = 0; mf < 2; mf++) {
                int r0 = wm * 32 + mf * 16;
                uint32_t ro = (uint32_t)(r0 + a_row) * PITCH + kb + a_kB;
                uint32_t a1f[4], a0f[4];
                LDMATRIX_X4(a1f[0], a1f[1], a1f[2], a1f[3], sb + A1_OFF + ro);
                LDMATRIX_X4(a0f[0], a0f[1], a0f[2], a0f[3], sb + A0_OFF + ro);
#pragma unroll
                for (int nf = 0; nf < 4; nf++) {
                    MMA_S8(P2[mf][nf], a1f, b1f[nf]);
                    MMA_S8(P1[mf][nf], a1f, b0f[nf]);
                    MMA_S8(P1[mf][nf], a0f, b1f[nf]);
                }
            }
        }
    }

    // epilogue: per-row (A) x per-col (B) scales
    float lmax = 0.f;
#pragma unroll
    for (int mf = 0; mf < 2; mf++) {
        int r0 = bm + wm * 32 + mf * 16 + gr;
        float ra = FUSED ? g_xsc[r0] : sA;
        float rb = FUSED ? g_xsc[r0 + 8] : sA;
#pragma unroll
        for (int nf = 0; nf < 4; nf++) {
            int cc = bn + wn * 32 + nf * 8 + tg;
            float cs0 = wscp[cc] * qi2;
            float cs1 = wscp[cc + 1] * qi2;
            float cv[4];
            cv[0] = ra * cs0 * (16384.0f * (float)P2[mf][nf][0] + 128.0f * (float)P1[mf][nf][0]);
            cv[1] = ra * cs1 * (16384.0f * (float)P2[mf][nf][1] + 128.0f * (float)P1[mf][nf][1]);
            cv[2] = rb * cs0 * (16384.0f * (float)P2[mf][nf][2] + 128.0f * (float)P1[mf][nf][2]);
            cv[3] = rb * cs1 * (16384.0f * (float)P2[mf][nf][3] + 128.0f * (float)P1[mf][nf][3]);
#pragma unroll
            for (int q = 0; q < 4; q++) {
                if (FUSED && vmax) lmax = fmaxf(lmax, fabsf(cv[q]));
                if (FUSED && sigmoid) cv[q] = 1.f / (1.f + __expf(-cv[q]));
            }
            *reinterpret_cast<float2*>(C + (size_t)r0 * HIDDEN + cc) = make_float2(cv[0], cv[1]);
            *reinterpret_cast<float2*>(C + (size_t)(r0 + 8) * HIDDEN + cc) = make_float2(cv[2], cv[3]);
        }
    }

    if (FUSED && vmax) {
        __syncthreads();
#pragma unroll
        for (int o = 16; o > 0; o >>= 1)
            lmax = fmaxf(lmax, __shfl_xor_sync(0xFFFFFFFF, lmax, o));
        if (lane == 0) atomicMax(&s_vmax, __float_as_uint(lmax));
        __syncthreads();
        if (tid == 0) atomicMax(&g_svb, s_vmax);
    }
}

// ---------------------------------------------------------------------------
// 3) Fused chunk-parallel WKV scan: phase1 + grid barrier + phase2 (KS warp
//    scan) + grid barrier + phase3, all in one launch. Math identical to R12.
// ---------------------------------------------------------------------------
__global__ __launch_bounds__(WKV_THREADS, 4)
void wkv_fused(const float* __restrict__ td, const float* __restrict__ tf) {
    const int tid = threadIdx.x;
    const int gthread = blockIdx.x * WKV_THREADS + tid;   // 0..65535

    // ---- phase 1: chunk summaries (one item per thread) ----
    {
        int idx = gthread;
        int h4 = (idx & 255) * 4;
        int bc = idx >> 8;
        int c = bc & (NCHUNK - 1);
        int b = bc >> 5;

        float4 w4 = *reinterpret_cast<const float4*>(td + h4);
        const float wv[4] = {w4.x, w4.y, w4.z, w4.w};

        const size_t base = ((size_t)b * SEQ + (size_t)c * LCHUNK) * HIDDEN + h4;
        const float* kp = g_k + base;
        const float* vp = g_v + base;

        float aa[4], bb[4], pp[4];
#pragma unroll
        for (int j = 0; j < 4; j++) { aa[j] = 0.f; bb[j] = 0.f; pp[j] = NEG_INF; }

#pragma unroll 2
        for (int t = 0; t < LCHUNK; t++) {
            float4 k4 = *reinterpret_cast<const float4*>(kp + (size_t)t * HIDDEN);
            float4 v4 = *reinterpret_cast<const float4*>(vp + (size_t)t * HIDDEN);
            float kf[4] = {k4.x, k4.y, k4.z, k4.w};
            float vf[4] = {v4.x, v4.y, v4.z, v4.w};
#pragma unroll
            for (int j = 0; j < 4; j++) {
                float ww2 = wv[j] + pp[j];
                float p2 = fmaxf(ww2, kf[j]);
                float e1 = __expf(ww2 - p2);
                float e2 = __expf(kf[j] - p2);
                aa[j] = e1 * aa[j] + e2 * vf[j];
                bb[j] = e1 * bb[j] + e2;
                pp[j] = p2;
            }
        }
        int s = bc * HIDDEN + h4;
        *reinterpret_cast<float4*>(g_saa + s) = make_float4(aa[0], aa[1], aa[2], aa[3]);
        *reinterpret_cast<float4*>(g_sbb + s) = make_float4(bb[0], bb[1], bb[2], bb[3]);
        *reinterpret_cast<float4*>(g_spp + s) = make_float4(pp[0], pp[1], pp[2], pp[3]);
    }

    grid_barrier(&g_bar1);

    // ---- phase 2: Kogge-Stone warp scan (2048 warps x 4 channels each) ----
    {
        int wbase = gthread >> 5;           // 0..2047
        int lane = tid & 31;
#pragma unroll 1
        for (int it = 0; it < 4; it++) {
            int gwarp = wbase + it * 2048;  // channel index
            int h = gwarp & (HIDDEN - 1);
            int b = gwarp >> 10;
            const float w = td[h];

            int s = (b * NCHUNK + lane) * HIDDEN + h;
            float aa = g_saa[s], bb = g_sbb[s], pp = g_spp[s];

#pragma unroll
            for (int d = 1; d < NCHUNK; d <<= 1) {
                float oaa = __shfl_up_sync(0xFFFFFFFF, aa, d);
                float obb = __shfl_up_sync(0xFFFFFFFF, bb, d);
                float opp = __shfl_up_sync(0xFFFFFFFF, pp, d);
                if (lane >= d) {
                    float sp = opp + w * (float)(d * LCHUNK);
                    float p = fmaxf(sp, pp);
                    float e1 = __expf(sp - p);
                    float e2 = __expf(pp - p);
                    aa = e1 * oaa + e2 * aa;
                    bb = e1 * obb + e2 * bb;
                    pp = p;
                }
            }

            float exaa = __shfl_up_sync(0xFFFFFFFF, aa, 1);
            float exbb = __shfl_up_sync(0xFFFFFFFF, bb, 1);
            float expp = __shfl_up_sync(0xFFFFFFFF, pp, 1);
            if (lane == 0) { exaa = 0.f; exbb = 0.f; expp = NEG_INF; }
            g_iaa[s] = exaa;
            g_ibb[s] = exbb;
            g_ipp[s] = expp;
        }
    }

    grid_barrier(&g_bar2);

    // ---- phase 3: rescan with exact prefix, write quantized r*wkv ----
    {
        int idx = gthread;
        int h4 = (idx & 255) * 4;
        int bc = idx >> 8;
        int c = bc & (NCHUNK - 1);
        int b = bc >> 5;

        float4 w4 = *reinterpret_cast<const float4*>(td + h4);
        float4 u4 = *reinterpret_cast<const float4*>(tf + h4);
        const float wv[4] = {w4.x, w4.y, w4.z, w4.w};
        const float uv[4] = {u4.x, u4.y, u4.z, u4.w};

        float sv = __uint_as_float(g_svb);
        float inv = (sv > 0.f) ? (QMAXF / sv) : 0.f;

        const size_t base = ((size_t)b * SEQ + (size_t)c * LCHUNK) * HIDDEN + h4;
        const float* kp = g_k + base;
        const float* vp = g_v + base;
        const float* rp = g_r + base;

        int s = bc * HIDDEN + h4;
        float4 a4 = *reinterpret_cast<const float4*>(g_iaa + s);
        float4 b4 = *reinterpret_cast<const float4*>(g_ibb + s);
        float4 p4 = *reinterpret_cast<const float4*>(g_ipp + s);
        float aa[4] = {a4.x, a4.y, a4.z, a4.w};
        float bb[4] = {b4.x, b4.y, b4.z, b4.w};
        float pp[4] = {p4.x, p4.y, p4.z, p4.w};

#pragma unroll 2
        for (int t = 0; t < LCHUNK; t++) {
            size_t off = (size_t)t * HIDDEN;
            float4 k4 = *reinterpret_cast<const float4*>(kp + off);
            float4 v4 = *reinterpret_cast<const float4*>(vp + off);
            float4 r4 = *reinterpret_cast<const float4*>(rp + off);
            float kf[4] = {k4.x, k4.y, k4.z, k4.w};
            float vf[4] = {v4.x, v4.y, v4.z, v4.w};
            float rf[4] = {r4.x, r4.y, r4.z, r4.w};
            uint32_t o1 = 0, o0 = 0;
#pragma unroll
            for (int j = 0; j < 4; j++) {
                float ww = uv[j] + kf[j];
                float p = fmaxf(pp[j], ww);
                float e1 = __expf(pp[j] - p);
                float e2 = __expf(ww - p);
                float wkv = (e1 * aa[j] + e2 * vf[j]) / (e1 * bb[j] + e2 + 1e-9f);
                float o = rf[j] * wkv;

                float q = rintf(o * inv);
                q = fminf(fmaxf(q, -QMAXF), QMAXF);
                float q1 = rintf(q * 0.0078125f);
                float q0 = q - 128.0f * q1;
                o1 |= ((uint32_t)(uint8_t)(int8_t)(int)q1) << (j * 8);
                o0 |= ((uint32_t)(uint8_t)(int8_t)(int)q0) << (j * 8);

                float ww2 = wv[j] + pp[j];
                float p2 = fmaxf(ww2, kf[j]);
                float e1b = __expf(ww2 - p2);
                float e2b = __expf(kf[j] - p2);
                aa[j] = e1b * aa[j] + e2b * vf[j];
                bb[j] = e1b * bb[j] + e2b;
                pp[j] = p2;
            }
            *reinterpret_cast<uint32_t*>(g_o1 + base + off) = o1;
            *reinterpret_cast<uint32_t*>(g_o0 + base + off) = o0;
        }
    }
}

// ---------------------------------------------------------------------------
// Launch
// ---------------------------------------------------------------------------
extern "C" void kernel_launch(void* const* d_in, const int* in_sizes, int n_in,
                              void* d_out, int out_size) {
    const float* x  = (const float*)d_in[0];
    const float* td = (const float*)d_in[1];
    const float* tf = (const float*)d_in[2];
    const float* mk = (const float*)d_in[3];
    const float* mv = (const float*)d_in[4];
    const float* mr = (const float*)d_in[5];
    const float* Wk = (const float*)d_in[6];
    const float* Wv = (const float*)d_in[7];
    const float* Wr = (const float*)d_in[8];
    const float* Wo = (const float*)d_in[9];
    float* out = (float*)d_out;

    cudaFuncSetAttribute(gemm_imma<true>,  cudaFuncAttributeMaxDynamicSharedMemorySize, SMEM_TOTAL);
    cudaFuncSetAttribute(gemm_imma<false>, cudaFuncAttributeMaxDynamicSharedMemorySize, SMEM_TOTAL);

    // 1) prep (resets g_svb + barrier counters)
    prep_quant<<<MTOT + 4 * HIDDEN, 256>>>(x, mk, mv, mr, Wk, Wv, Wr, Wo);

    // 2) fused k/v/r projections (int8 imma)
    dim3 ggrid(HIDDEN / BN, MTOT / BM, 3);   // (8, 128, 3)
    gemm_imma<true><<<ggrid, GTHREADS, SMEM_TOTAL>>>(nullptr);

    // 3) fused chunk-parallel wkv (phase1+2+3, software grid barriers)
    wkv_fused<<<WKV_BLOCKS, WKV_THREADS>>>(td, tf);

    // 4) output projection
    dim3 ogrid(HIDDEN / BN, MTOT / BM, 1);
    gemm_imma<false><<<ogrid, GTHREADS, SMEM_TOTAL>>>(out);
}